// round 3
// baseline (speedup 1.0000x reference)
#include <cuda_runtime.h>
#include <cuda_fp16.h>
#include <cstdint>

#define N_NODES 100000
#define N_EDGES 3200000
#define N_RELS  8
#define F_DIM   64

// fp16 per-relation transformed features: 8 * 100000 * 64 * 2 B = 102.4 MB
__device__ __half g_XWh[(size_t)N_RELS * N_NODES * F_DIM];

__device__ __forceinline__ uint32_t f2tf32(float f) {
    uint32_t r;
    asm("cvt.rna.tf32.f32 %0, %1;" : "=r"(r) : "f"(f));
    return r;
}

// ---------------------------------------------------------------------------
// Kernel 1: XWh[r] = fp16(X @ W[r]) via mma.sync m16n8k8 tf32.
// Block: 256 threads (8 warps) covering 64 rows x 64 cols.
//   warp w: rows (w%4)*16 .. +16, col half (w/4)*32 .. +32
// Per warp: 4 n-tiles x 8 k-steps = 32 mma.
// ---------------------------------------------------------------------------
__global__ __launch_bounds__(256) void xw_kernel(const float* __restrict__ X,
                                                 const float* __restrict__ W,
                                                 __half* __restrict__ XWh) {
    const int r  = blockIdx.y;
    const int n0blk = blockIdx.x * 64;

    __shared__ float Xs[64][65];
    __shared__ float Ws[64][65];

    // Load W[r] (64x64) into Ws[k][n]
    for (int i = threadIdx.x; i < 64 * 64; i += 256) {
        Ws[i >> 6][i & 63] = W[r * 64 * 64 + i];
    }
    // Load X tile (64 rows), guarded
    for (int i = threadIdx.x; i < 64 * 64; i += 256) {
        int row = i >> 6, col = i & 63;
        int n = n0blk + row;
        Xs[row][col] = (n < N_NODES) ? X[(size_t)n * 64 + col] : 0.0f;
    }
    __syncthreads();

    const int warp = threadIdx.x >> 5;
    const int lane = threadIdx.x & 31;
    const int g = lane >> 2;       // groupID (0..7)
    const int t = lane & 3;        // thread in group (0..3)

    const int r0 = (warp & 3) * 16;        // row offset within 64-row tile
    const int ch = (warp >> 2) * 32;       // col half offset

    float acc[4][4];
#pragma unroll
    for (int j = 0; j < 4; j++)
#pragma unroll
        for (int c = 0; c < 4; c++) acc[j][c] = 0.0f;

#pragma unroll
    for (int kk = 0; kk < 8; kk++) {
        const int k0 = kk * 8;
        uint32_t a0 = f2tf32(Xs[r0 + g][k0 + t]);
        uint32_t a1 = f2tf32(Xs[r0 + g + 8][k0 + t]);
        uint32_t a2 = f2tf32(Xs[r0 + g][k0 + t + 4]);
        uint32_t a3 = f2tf32(Xs[r0 + g + 8][k0 + t + 4]);
#pragma unroll
        for (int j = 0; j < 4; j++) {
            const int n0 = ch + j * 8;
            uint32_t b0 = f2tf32(Ws[k0 + t][n0 + g]);
            uint32_t b1 = f2tf32(Ws[k0 + t + 4][n0 + g]);
            asm volatile(
                "mma.sync.aligned.m16n8k8.row.col.f32.tf32.tf32.f32 "
                "{%0,%1,%2,%3}, {%4,%5,%6,%7}, {%8,%9}, {%0,%1,%2,%3};"
                : "+f"(acc[j][0]), "+f"(acc[j][1]), "+f"(acc[j][2]), "+f"(acc[j][3])
                : "r"(a0), "r"(a1), "r"(a2), "r"(a3), "r"(b0), "r"(b1));
        }
    }

    // Store fp16: c0/c1 -> row g, cols 2t,2t+1 ; c2/c3 -> row g+8
    __half* base = XWh + (size_t)r * N_NODES * 64;
#pragma unroll
    for (int j = 0; j < 4; j++) {
        const int col = ch + j * 8 + 2 * t;
        const int row_a = n0blk + r0 + g;
        const int row_b = row_a + 8;
        __half2 lo = __floats2half2_rn(acc[j][0], acc[j][1]);
        __half2 hi = __floats2half2_rn(acc[j][2], acc[j][3]);
        if (row_a < N_NODES)
            *reinterpret_cast<__half2*>(base + (size_t)row_a * 64 + col) = lo;
        if (row_b < N_NODES)
            *reinterpret_cast<__half2*>(base + (size_t)row_b * 64 + col) = hi;
    }
}

// ---------------------------------------------------------------------------
// Kernel 2: edge gather (fp16) + scale + fp32 scatter-add.
// 8 threads per edge; each thread handles 8 halves (16 B) -> 2x red.v4.f32.
// ---------------------------------------------------------------------------
__global__ __launch_bounds__(256) void edge_kernel(const __half* __restrict__ XWh,
                                                   const float* __restrict__ A,
                                                   const int*   __restrict__ src,
                                                   const int*   __restrict__ dst,
                                                   const int*   __restrict__ etype,
                                                   float* __restrict__ Y) {
    const long long gid = (long long)blockIdx.x * blockDim.x + threadIdx.x;
    const int e  = (int)(gid >> 3);      // edge index
    const int f8 = (int)(gid & 7);       // which 8-half chunk
    if (e >= N_EDGES) return;

    const int s = src[e];
    const int d = dst[e];
    const int r = etype[e];
    const float a = A[e];

    const uint4 raw = *reinterpret_cast<const uint4*>(
        XWh + ((size_t)r * N_NODES + (size_t)s) * 64 + f8 * 8);

    const __half2* h = reinterpret_cast<const __half2*>(&raw);
    float2 p0 = __half22float2(h[0]);
    float2 p1 = __half22float2(h[1]);
    float2 p2 = __half22float2(h[2]);
    float2 p3 = __half22float2(h[3]);

    float m0 = p0.x * a, m1 = p0.y * a, m2 = p1.x * a, m3 = p1.y * a;
    float m4 = p2.x * a, m5 = p2.y * a, m6 = p3.x * a, m7 = p3.y * a;

    float* out = Y + (size_t)d * 64 + f8 * 8;
    asm volatile("red.global.add.v4.f32 [%0], {%1, %2, %3, %4};"
                 :: "l"(out), "f"(m0), "f"(m1), "f"(m2), "f"(m3) : "memory");
    asm volatile("red.global.add.v4.f32 [%0], {%1, %2, %3, %4};"
                 :: "l"(out + 4), "f"(m4), "f"(m5), "f"(m6), "f"(m7) : "memory");
}

// ---------------------------------------------------------------------------
extern "C" void kernel_launch(void* const* d_in, const int* in_sizes, int n_in,
                              void* d_out, int out_size) {
    const float* X     = (const float*)d_in[0];
    const float* W     = (const float*)d_in[1];
    const float* A     = (const float*)d_in[2];
    const int*   src   = (const int*)d_in[3];
    const int*   dst   = (const int*)d_in[4];
    const int*   etype = (const int*)d_in[5];
    float* Y = (float*)d_out;

    __half* XWh = nullptr;
    cudaGetSymbolAddress((void**)&XWh, g_XWh);

    cudaMemsetAsync(Y, 0, (size_t)N_NODES * F_DIM * sizeof(float), 0);

    dim3 grid_xw((N_NODES + 63) / 64, N_RELS);
    xw_kernel<<<grid_xw, 256>>>(X, W, XWh);

    long long total_threads = (long long)N_EDGES * 8;
    int blocks = (int)((total_threads + 255) / 256);
    edge_kernel<<<blocks, 256>>>(XWh, A, src, dst, etype, Y);
}

// round 5
// speedup vs baseline: 1.7098x; 1.7098x over previous
#include <cuda_runtime.h>
#include <cuda_fp16.h>
#include <cstdint>

#define N_NODES 100000
#define N_EDGES 3200000
#define N_RELS  8
#define F_DIM   64

#define SCAN_BLK 1024
#define SCAN_NBLK ((N_NODES + SCAN_BLK - 1) / SCAN_BLK)   // 98

// fp16 per-relation transformed features: 8 * 100000 * 64 * 2 B = 102.4 MB
__device__ __half g_XWh[(size_t)N_RELS * N_NODES * F_DIM];
// CSR-by-dst build
__device__ int g_count[N_NODES];
__device__ int g_tmp[N_NODES];        // per-block inclusive scan
__device__ int g_start[N_NODES];      // exclusive row start
__device__ int g_cursor[N_NODES];     // scatter cursors
__device__ int g_blocktot[SCAN_NBLK];
__device__ int g_blockoff[SCAN_NBLK];
// packed edge records sorted by dst: lo32 = src | (rel<<17), hi32 = bits(A)
__device__ unsigned long long g_recs[N_EDGES];

// ---------------------------------------------------------------------------
// Kernel 1: XWh[r] = fp16(X @ W[r]) via mma.sync m16n8k16 f16 (fp32 accum).
// Block: 256 thr = 8 warps over a 64x64 tile. Conflict-free smem (pitch 72 h).
// ---------------------------------------------------------------------------
__global__ __launch_bounds__(256) void xw_kernel(const float* __restrict__ X,
                                                 const float* __restrict__ W,
                                                 __half* __restrict__ XWh) {
    const int r = blockIdx.y;
    const int n0blk = blockIdx.x * 64;

    __shared__ __half Xh[64][72];   // X tile rows, 144B pitch
    __shared__ __half Wt[64][72];   // W[r] transposed: Wt[n][k]

    // Load X tile as fp16 (float2 -> half2), coalesced
    for (int i = threadIdx.x; i < 64 * 32; i += 256) {
        int row = i >> 5, cp = i & 31;           // cp = column pair
        int n = n0blk + row;
        float2 v = (n < N_NODES)
            ? *reinterpret_cast<const float2*>(X + (size_t)n * 64 + cp * 2)
            : make_float2(0.0f, 0.0f);
        *reinterpret_cast<__half2*>(&Xh[row][cp * 2]) = __floats2half2_rn(v.x, v.y);
    }
    // Load W[r] (k-major) transposed into Wt[n][k]
    for (int i = threadIdx.x; i < 64 * 64; i += 256) {
        int k = i >> 6, n = i & 63;
        Wt[n][k] = __float2half_rn(W[r * 4096 + i]);
    }
    __syncthreads();

    const int warp = threadIdx.x >> 5;
    const int lane = threadIdx.x & 31;
    const int g = lane >> 2;          // 0..7
    const int t = lane & 3;           // 0..3

    const int r0 = (warp & 3) * 16;   // row offset in tile
    const int ch = (warp >> 2) * 32;  // column half

    float acc[4][4];
#pragma unroll
    for (int j = 0; j < 4; j++)
#pragma unroll
        for (int c = 0; c < 4; c++) acc[j][c] = 0.0f;

#pragma unroll
    for (int kk = 0; kk < 4; kk++) {
        const int k0 = kk * 16;
        uint32_t a0 = *reinterpret_cast<const uint32_t*>(&Xh[r0 + g    ][k0 + 2 * t    ]);
        uint32_t a1 = *reinterpret_cast<const uint32_t*>(&Xh[r0 + g + 8][k0 + 2 * t    ]);
        uint32_t a2 = *reinterpret_cast<const uint32_t*>(&Xh[r0 + g    ][k0 + 2 * t + 8]);
        uint32_t a3 = *reinterpret_cast<const uint32_t*>(&Xh[r0 + g + 8][k0 + 2 * t + 8]);
#pragma unroll
        for (int j = 0; j < 4; j++) {
            const int n0 = ch + j * 8;
            uint32_t b0 = *reinterpret_cast<const uint32_t*>(&Wt[n0 + g][k0 + 2 * t    ]);
            uint32_t b1 = *reinterpret_cast<const uint32_t*>(&Wt[n0 + g][k0 + 2 * t + 8]);
            asm volatile(
                "mma.sync.aligned.m16n8k16.row.col.f32.f16.f16.f32 "
                "{%0,%1,%2,%3}, {%4,%5,%6,%7}, {%8,%9}, {%0,%1,%2,%3};"
                : "+f"(acc[j][0]), "+f"(acc[j][1]), "+f"(acc[j][2]), "+f"(acc[j][3])
                : "r"(a0), "r"(a1), "r"(a2), "r"(a3), "r"(b0), "r"(b1));
        }
    }

    __half* base = XWh + (size_t)r * N_NODES * 64;
#pragma unroll
    for (int j = 0; j < 4; j++) {
        const int col = ch + j * 8 + 2 * t;
        const int row_a = n0blk + r0 + g;
        const int row_b = row_a + 8;
        __half2 lo = __floats2half2_rn(acc[j][0], acc[j][1]);
        __half2 hi = __floats2half2_rn(acc[j][2], acc[j][3]);
        if (row_a < N_NODES)
            *reinterpret_cast<__half2*>(base + (size_t)row_a * 64 + col) = lo;
        if (row_b < N_NODES)
            *reinterpret_cast<__half2*>(base + (size_t)row_b * 64 + col) = hi;
    }
}

// ---------------------------------------------------------------------------
// CSR build: histogram -> scan (3 steps) -> scatter packed records
// ---------------------------------------------------------------------------
__global__ __launch_bounds__(256) void hist_kernel(const int* __restrict__ dst) {
    int e = blockIdx.x * 256 + threadIdx.x;
    if (e < N_EDGES) atomicAdd(&g_count[dst[e]], 1);
}

__global__ __launch_bounds__(SCAN_BLK) void scan1_kernel() {
    __shared__ int s[SCAN_BLK];
    int t = threadIdx.x;
    int i = blockIdx.x * SCAN_BLK + t;
    int v = (i < N_NODES) ? g_count[i] : 0;
    s[t] = v;
    __syncthreads();
    for (int off = 1; off < SCAN_BLK; off <<= 1) {
        int add = (t >= off) ? s[t - off] : 0;
        __syncthreads();
        s[t] += add;
        __syncthreads();
    }
    if (i < N_NODES) g_tmp[i] = s[t];                 // inclusive within block
    if (t == SCAN_BLK - 1) g_blocktot[blockIdx.x] = s[t];
}

__global__ __launch_bounds__(128) void scan2_kernel() {
    __shared__ int s[128];
    int t = threadIdx.x;
    s[t] = (t < SCAN_NBLK) ? g_blocktot[t] : 0;
    __syncthreads();
    for (int off = 1; off < 128; off <<= 1) {
        int add = (t >= off) ? s[t - off] : 0;
        __syncthreads();
        s[t] += add;
        __syncthreads();
    }
    if (t < SCAN_NBLK) g_blockoff[t] = s[t] - g_blocktot[t];  // exclusive
}

__global__ __launch_bounds__(SCAN_BLK) void scan3_kernel() {
    int i = blockIdx.x * SCAN_BLK + threadIdx.x;
    if (i < N_NODES) {
        int st = g_tmp[i] - g_count[i] + g_blockoff[blockIdx.x];
        g_start[i] = st;
        g_cursor[i] = st;
    }
}

__global__ __launch_bounds__(256) void scatter_kernel(const float* __restrict__ A,
                                                      const int* __restrict__ src,
                                                      const int* __restrict__ dst,
                                                      const int* __restrict__ etype) {
    int e = blockIdx.x * 256 + threadIdx.x;
    if (e >= N_EDGES) return;
    int d = dst[e];
    int p = atomicAdd(&g_cursor[d], 1);
    unsigned key = (unsigned)src[e] | ((unsigned)etype[e] << 17);
    unsigned long long rec = (unsigned long long)key |
                             ((unsigned long long)__float_as_uint(A[e]) << 32);
    g_recs[p] = rec;
}

// ---------------------------------------------------------------------------
// Gather: one warp per dst node. Each edge: broadcast record load + one
// coalesced 128B fp16 row load; register accumulation; single Y write.
// ---------------------------------------------------------------------------
__global__ __launch_bounds__(256) void gather_kernel(const __half* __restrict__ XWh,
                                                     float* __restrict__ Y) {
    const int node = blockIdx.x * 8 + (threadIdx.x >> 5);
    if (node >= N_NODES) return;
    const int lane = threadIdx.x & 31;

    const int s = g_start[node];
    const int cnt = g_count[node];
    const int end = s + cnt;

    float acc0 = 0.0f, acc1 = 0.0f;

    int i = s;
    for (; i + 2 <= end; i += 2) {
        unsigned long long r0 = g_recs[i];
        unsigned long long r1 = g_recs[i + 1];
        unsigned k0 = (unsigned)r0, k1 = (unsigned)r1;
        float a0 = __uint_as_float((unsigned)(r0 >> 32));
        float a1 = __uint_as_float((unsigned)(r1 >> 32));
        size_t row0 = (size_t)(k0 >> 17) * N_NODES + (k0 & 0x1FFFF);
        size_t row1 = (size_t)(k1 >> 17) * N_NODES + (k1 & 0x1FFFF);
        __half2 h0 = *(reinterpret_cast<const __half2*>(XWh + row0 * 64) + lane);
        __half2 h1 = *(reinterpret_cast<const __half2*>(XWh + row1 * 64) + lane);
        float2 f0 = __half22float2(h0);
        float2 f1 = __half22float2(h1);
        acc0 = fmaf(f0.x, a0, acc0);
        acc1 = fmaf(f0.y, a0, acc1);
        acc0 = fmaf(f1.x, a1, acc0);
        acc1 = fmaf(f1.y, a1, acc1);
    }
    if (i < end) {
        unsigned long long r0 = g_recs[i];
        unsigned k0 = (unsigned)r0;
        float a0 = __uint_as_float((unsigned)(r0 >> 32));
        size_t row0 = (size_t)(k0 >> 17) * N_NODES + (k0 & 0x1FFFF);
        __half2 h0 = *(reinterpret_cast<const __half2*>(XWh + row0 * 64) + lane);
        float2 f0 = __half22float2(h0);
        acc0 = fmaf(f0.x, a0, acc0);
        acc1 = fmaf(f0.y, a0, acc1);
    }

    *reinterpret_cast<float2*>(Y + (size_t)node * 64 + 2 * lane) =
        make_float2(acc0, acc1);
}

// ---------------------------------------------------------------------------
extern "C" void kernel_launch(void* const* d_in, const int* in_sizes, int n_in,
                              void* d_out, int out_size) {
    const float* X     = (const float*)d_in[0];
    const float* W     = (const float*)d_in[1];
    const float* A     = (const float*)d_in[2];
    const int*   src   = (const int*)d_in[3];
    const int*   dst   = (const int*)d_in[4];
    const int*   etype = (const int*)d_in[5];
    float* Y = (float*)d_out;

    __half* XWh = nullptr;
    cudaGetSymbolAddress((void**)&XWh, g_XWh);
    void* countp = nullptr;
    cudaGetSymbolAddress(&countp, g_count);

    // CSR build chain
    cudaMemsetAsync(countp, 0, N_NODES * sizeof(int), 0);
    int eblocks = (N_EDGES + 255) / 256;
    hist_kernel<<<eblocks, 256>>>(dst);
    scan1_kernel<<<SCAN_NBLK, SCAN_BLK>>>();
    scan2_kernel<<<1, 128>>>();
    scan3_kernel<<<SCAN_NBLK, SCAN_BLK>>>();
    scatter_kernel<<<eblocks, 256>>>(A, src, dst, etype);

    // XW table (independent of CSR chain; stream-serialized is fine)
    dim3 grid_xw((N_NODES + 63) / 64, N_RELS);
    xw_kernel<<<grid_xw, 256>>>(X, W, XWh);

    // Warp-per-node gather (writes every Y element; no memset needed)
    gather_kernel<<<(N_NODES + 7) / 8, 256>>>(XWh, Y);
}

// round 6
// speedup vs baseline: 2.0272x; 1.1856x over previous
#include <cuda_runtime.h>
#include <cuda_fp16.h>
#include <cstdint>

#define N_NODES 100000
#define N_EDGES 3200000
#define N_RELS  8
#define F_DIM   64

#define SCAN_BLK 1024
#define SCAN_NBLK ((N_NODES + SCAN_BLK - 1) / SCAN_BLK)   // 98

// fp16 per-relation transformed features: 8 * 100000 * 64 * 2 B = 102.4 MB
__device__ __half g_XWh[(size_t)N_RELS * N_NODES * F_DIM];
// fp16 transposed weights: g_Wht[r][n][k]
__device__ __half g_Wht[N_RELS * F_DIM * F_DIM];
// CSR-by-dst build
__device__ int g_count[N_NODES];
__device__ int g_tmp[N_NODES];
__device__ int g_start[N_NODES];
__device__ int g_cursor[N_NODES];
__device__ int g_blocktot[SCAN_NBLK];
__device__ int g_blockoff[SCAN_NBLK];
// packed edge records grouped by dst: lo32 = src | (rel<<17), hi32 = bits(A)
__device__ unsigned long long g_recs[N_EDGES];

// ---------------------------------------------------------------------------
// W pre-convert + transpose: g_Wht[r][n][k] = fp16(W[r][k][n])
// ---------------------------------------------------------------------------
__global__ __launch_bounds__(256) void wconv_kernel(const float* __restrict__ W) {
    int i = blockIdx.x * 256 + threadIdx.x;    // i over 8*64*64
    if (i >= N_RELS * 64 * 64) return;
    int r = i >> 12;
    int n = (i >> 6) & 63;
    int k = i & 63;
    g_Wht[i] = __float2half_rn(W[r * 4096 + k * 64 + n]);
}

// ---------------------------------------------------------------------------
// Kernel 1: XWh[r] = fp16(X @ W[r]) — one X tile load, loop over 8 relations.
// Block: 256 thr = 8 warps over a 64x64 tile. Conflict-free smem (pitch 72 h).
// ---------------------------------------------------------------------------
__global__ __launch_bounds__(256) void xw_kernel(const float* __restrict__ X,
                                                 __half* __restrict__ XWh) {
    const int n0blk = blockIdx.x * 64;

    __shared__ __half Xh[64][72];   // X tile rows, 144B pitch
    __shared__ __half Wt[64][72];   // Wt[n][k] for current relation

    // Load X tile as fp16 (float2 -> half2), coalesced — ONCE
    for (int i = threadIdx.x; i < 64 * 32; i += 256) {
        int row = i >> 5, cp = i & 31;
        int n = n0blk + row;
        float2 v = (n < N_NODES)
            ? *reinterpret_cast<const float2*>(X + (size_t)n * 64 + cp * 2)
            : make_float2(0.0f, 0.0f);
        *reinterpret_cast<__half2*>(&Xh[row][cp * 2]) = __floats2half2_rn(v.x, v.y);
    }

    const int warp = threadIdx.x >> 5;
    const int lane = threadIdx.x & 31;
    const int g = lane >> 2;          // 0..7
    const int t = lane & 3;           // 0..3
    const int r0 = (warp & 3) * 16;   // row offset in tile
    const int ch = (warp >> 2) * 32;  // column half

    for (int r = 0; r < N_RELS; r++) {
        __syncthreads();   // protect Wt reuse + first-iter X readiness
        // Load Wt[n][k] for relation r (coalesced half2, conflict-free)
        for (int i = threadIdx.x; i < 64 * 32; i += 256) {
            int n = i >> 5, kp = i & 31;
            *reinterpret_cast<__half2*>(&Wt[n][kp * 2]) =
                *reinterpret_cast<const __half2*>(&g_Wht[r * 4096 + n * 64 + kp * 2]);
        }
        __syncthreads();

        float acc[4][4];
#pragma unroll
        for (int j = 0; j < 4; j++)
#pragma unroll
            for (int c = 0; c < 4; c++) acc[j][c] = 0.0f;

#pragma unroll
        for (int kk = 0; kk < 4; kk++) {
            const int k0 = kk * 16;
            uint32_t a0 = *reinterpret_cast<const uint32_t*>(&Xh[r0 + g    ][k0 + 2 * t    ]);
            uint32_t a1 = *reinterpret_cast<const uint32_t*>(&Xh[r0 + g + 8][k0 + 2 * t    ]);
            uint32_t a2 = *reinterpret_cast<const uint32_t*>(&Xh[r0 + g    ][k0 + 2 * t + 8]);
            uint32_t a3 = *reinterpret_cast<const uint32_t*>(&Xh[r0 + g + 8][k0 + 2 * t + 8]);
#pragma unroll
            for (int j = 0; j < 4; j++) {
                const int n0 = ch + j * 8;
                uint32_t b0 = *reinterpret_cast<const uint32_t*>(&Wt[n0 + g][k0 + 2 * t    ]);
                uint32_t b1 = *reinterpret_cast<const uint32_t*>(&Wt[n0 + g][k0 + 2 * t + 8]);
                asm volatile(
                    "mma.sync.aligned.m16n8k16.row.col.f32.f16.f16.f32 "
                    "{%0,%1,%2,%3}, {%4,%5,%6,%7}, {%8,%9}, {%0,%1,%2,%3};"
                    : "+f"(acc[j][0]), "+f"(acc[j][1]), "+f"(acc[j][2]), "+f"(acc[j][3])
                    : "r"(a0), "r"(a1), "r"(a2), "r"(a3), "r"(b0), "r"(b1));
            }
        }

        __half* base = XWh + (size_t)r * N_NODES * 64;
#pragma unroll
        for (int j = 0; j < 4; j++) {
            const int col = ch + j * 8 + 2 * t;
            const int row_a = n0blk + r0 + g;
            const int row_b = row_a + 8;
            __half2 lo = __floats2half2_rn(acc[j][0], acc[j][1]);
            __half2 hi = __floats2half2_rn(acc[j][2], acc[j][3]);
            if (row_a < N_NODES)
                *reinterpret_cast<__half2*>(base + (size_t)row_a * 64 + col) = lo;
            if (row_b < N_NODES)
                *reinterpret_cast<__half2*>(base + (size_t)row_b * 64 + col) = hi;
        }
    }
}

// ---------------------------------------------------------------------------
// CSR build: histogram -> scan (3 steps) -> scatter packed records
// ---------------------------------------------------------------------------
__global__ __launch_bounds__(256) void hist_kernel(const int* __restrict__ dst) {
    int e = blockIdx.x * 256 + threadIdx.x;
    if (e < N_EDGES) atomicAdd(&g_count[dst[e]], 1);
}

__global__ __launch_bounds__(SCAN_BLK) void scan1_kernel() {
    __shared__ int s[SCAN_BLK];
    int t = threadIdx.x;
    int i = blockIdx.x * SCAN_BLK + t;
    int v = (i < N_NODES) ? g_count[i] : 0;
    s[t] = v;
    __syncthreads();
    for (int off = 1; off < SCAN_BLK; off <<= 1) {
        int add = (t >= off) ? s[t - off] : 0;
        __syncthreads();
        s[t] += add;
        __syncthreads();
    }
    if (i < N_NODES) g_tmp[i] = s[t];
    if (t == SCAN_BLK - 1) g_blocktot[blockIdx.x] = s[t];
}

__global__ __launch_bounds__(128) void scan2_kernel() {
    __shared__ int s[128];
    int t = threadIdx.x;
    s[t] = (t < SCAN_NBLK) ? g_blocktot[t] : 0;
    __syncthreads();
    for (int off = 1; off < 128; off <<= 1) {
        int add = (t >= off) ? s[t - off] : 0;
        __syncthreads();
        s[t] += add;
        __syncthreads();
    }
    if (t < SCAN_NBLK) g_blockoff[t] = s[t] - g_blocktot[t];
}

__global__ __launch_bounds__(SCAN_BLK) void scan3_kernel() {
    int i = blockIdx.x * SCAN_BLK + threadIdx.x;
    if (i < N_NODES) {
        int st = g_tmp[i] - g_count[i] + g_blockoff[blockIdx.x];
        g_start[i] = st;
        g_cursor[i] = st;
    }
}

__global__ __launch_bounds__(256) void scatter_kernel(const float* __restrict__ A,
                                                      const int* __restrict__ src,
                                                      const int* __restrict__ dst,
                                                      const int* __restrict__ etype) {
    int e = blockIdx.x * 256 + threadIdx.x;
    if (e >= N_EDGES) return;
    int d = dst[e];
    int p = atomicAdd(&g_cursor[d], 1);
    unsigned key = (unsigned)src[e] | ((unsigned)etype[e] << 17);
    unsigned long long rec = (unsigned long long)key |
                             ((unsigned long long)__float_as_uint(A[e]) << 32);
    g_recs[p] = rec;
}

// ---------------------------------------------------------------------------
// Gather: one warp per dst node, 4-edge unroll for MLP.
// ---------------------------------------------------------------------------
__global__ __launch_bounds__(256) void gather_kernel(const __half* __restrict__ XWh,
                                                     float* __restrict__ Y) {
    const int node = blockIdx.x * 8 + (threadIdx.x >> 5);
    if (node >= N_NODES) return;
    const int lane = threadIdx.x & 31;

    const int s = g_start[node];
    const int end = s + g_count[node];

    float acc0 = 0.0f, acc1 = 0.0f;

    int i = s;
    for (; i + 4 <= end; i += 4) {
        unsigned long long r0 = g_recs[i];
        unsigned long long r1 = g_recs[i + 1];
        unsigned long long r2 = g_recs[i + 2];
        unsigned long long r3 = g_recs[i + 3];
        unsigned k0 = (unsigned)r0, k1 = (unsigned)r1;
        unsigned k2 = (unsigned)r2, k3 = (unsigned)r3;
        float a0 = __uint_as_float((unsigned)(r0 >> 32));
        float a1 = __uint_as_float((unsigned)(r1 >> 32));
        float a2 = __uint_as_float((unsigned)(r2 >> 32));
        float a3 = __uint_as_float((unsigned)(r3 >> 32));
        size_t row0 = (size_t)(k0 >> 17) * N_NODES + (k0 & 0x1FFFF);
        size_t row1 = (size_t)(k1 >> 17) * N_NODES + (k1 & 0x1FFFF);
        size_t row2 = (size_t)(k2 >> 17) * N_NODES + (k2 & 0x1FFFF);
        size_t row3 = (size_t)(k3 >> 17) * N_NODES + (k3 & 0x1FFFF);
        __half2 h0 = *(reinterpret_cast<const __half2*>(XWh + row0 * 64) + lane);
        __half2 h1 = *(reinterpret_cast<const __half2*>(XWh + row1 * 64) + lane);
        __half2 h2 = *(reinterpret_cast<const __half2*>(XWh + row2 * 64) + lane);
        __half2 h3 = *(reinterpret_cast<const __half2*>(XWh + row3 * 64) + lane);
        float2 f0 = __half22float2(h0);
        float2 f1 = __half22float2(h1);
        float2 f2 = __half22float2(h2);
        float2 f3 = __half22float2(h3);
        acc0 = fmaf(f0.x, a0, acc0); acc1 = fmaf(f0.y, a0, acc1);
        acc0 = fmaf(f1.x, a1, acc0); acc1 = fmaf(f1.y, a1, acc1);
        acc0 = fmaf(f2.x, a2, acc0); acc1 = fmaf(f2.y, a2, acc1);
        acc0 = fmaf(f3.x, a3, acc0); acc1 = fmaf(f3.y, a3, acc1);
    }
    for (; i < end; i++) {
        unsigned long long r0 = g_recs[i];
        unsigned k0 = (unsigned)r0;
        float a0 = __uint_as_float((unsigned)(r0 >> 32));
        size_t row0 = (size_t)(k0 >> 17) * N_NODES + (k0 & 0x1FFFF);
        __half2 h0 = *(reinterpret_cast<const __half2*>(XWh + row0 * 64) + lane);
        float2 f0 = __half22float2(h0);
        acc0 = fmaf(f0.x, a0, acc0);
        acc1 = fmaf(f0.y, a0, acc1);
    }

    *reinterpret_cast<float2*>(Y + (size_t)node * 64 + 2 * lane) =
        make_float2(acc0, acc1);
}

// ---------------------------------------------------------------------------
extern "C" void kernel_launch(void* const* d_in, const int* in_sizes, int n_in,
                              void* d_out, int out_size) {
    const float* X     = (const float*)d_in[0];
    const float* W     = (const float*)d_in[1];
    const float* A     = (const float*)d_in[2];
    const int*   src   = (const int*)d_in[3];
    const int*   dst   = (const int*)d_in[4];
    const int*   etype = (const int*)d_in[5];
    float* Y = (float*)d_out;

    __half* XWh = nullptr;
    cudaGetSymbolAddress((void**)&XWh, g_XWh);
    void* countp = nullptr;
    cudaGetSymbolAddress(&countp, g_count);

    // CSR build chain
    cudaMemsetAsync(countp, 0, N_NODES * sizeof(int), 0);
    int eblocks = (N_EDGES + 255) / 256;
    hist_kernel<<<eblocks, 256>>>(dst);
    scan1_kernel<<<SCAN_NBLK, SCAN_BLK>>>();
    scan2_kernel<<<1, 128>>>();
    scan3_kernel<<<SCAN_NBLK, SCAN_BLK>>>();
    scatter_kernel<<<eblocks, 256>>>(A, src, dst, etype);

    // XW table: W preconvert then multi-relation GEMM
    wconv_kernel<<<(N_RELS * 64 * 64 + 255) / 256, 256>>>(W);
    xw_kernel<<<(N_NODES + 63) / 64, 256>>>(X, XWh);

    // Warp-per-node gather (writes every Y element; no memset needed)
    gather_kernel<<<(N_NODES + 7) / 8, 256>>>(XWh, Y);
}